// round 6
// baseline (speedup 1.0000x reference)
#include <cuda_runtime.h>
#include <cuda_bf16.h>

// PMF: out[p] = relu(dot(user_emb[user_ids[p]], item_emb[item_ids[p]])), D=64 fp32.
//
// R6: locality via cheap single-pass bucketing (R5's hist/scan/scatter pipeline
// cost ~60us; this replaces it with one bump-allocator scatter kernel).
//   K0: zero 512 bucket counters
//   K1: scatter packed (uid|iid|p) into fixed-capacity bucket slabs using
//       global atomicAdd bump allocators (ATOMG ~0.854cyc/op under contention)
//   K2: main gather-dot-relu, walking slabs bucket-major so concurrent CTAs
//       touch only a few MB of user rows -> user-row repeats hit L2.
// Out is indexed by original p (stored in the record) -> deterministic output.
// Fallback to direct R4 kernel if problem shape exceeds packing budget.

#define HIDDEN 64

#define BUCKETS 512
#define BSHIFT 11                       // bucket = uid >> 11
#define CAP_B 8192                      // slots per bucket (mean ~4090, +safety)
#define UID_BITS 20                     // pack: uid | iid<<20 | p<<37
#define IID_BITS 17

__device__ int g_cnt[BUCKETS];
__device__ unsigned long long g_pairs[BUCKETS * CAP_B];   // 32MB slab

// ---------------- K0: zero counters ----------------
__global__ void zero_kernel() {
    int i = threadIdx.x + blockIdx.x * blockDim.x;
    if (i < BUCKETS) g_cnt[i] = 0;
}

// ---------------- K1: single-pass scatter ----------------
#define SC_THREADS 256
#define SC_K 4
#define SC_TILE (SC_THREADS * SC_K)

__global__ __launch_bounds__(SC_THREADS)
void scatter_kernel(const int* __restrict__ user_ids,
                    const int* __restrict__ item_ids, int n)
{
    int base = blockIdx.x * SC_TILE;
    #pragma unroll
    for (int k = 0; k < SC_K; k++) {
        int i = base + k * SC_THREADS + threadIdx.x;
        if (i < n) {
            int uid = __ldg(&user_ids[i]);
            int iid = __ldg(&item_ids[i]);
            int b = uid >> BSHIFT;
            int pos = atomicAdd(&g_cnt[b], 1);
            unsigned long long rec =
                  (unsigned long long)(unsigned)uid
                | ((unsigned long long)(unsigned)iid << UID_BITS)
                | ((unsigned long long)(unsigned)i << (UID_BITS + IID_BITS));
            g_pairs[(long long)b * CAP_B + pos] = rec;
        }
    }
}

// ---------------- K2: main kernel over bucket slabs ----------------
#define THREADS 256
#define GROUPS_PER_BLOCK (THREADS / 16)            // 16
#define PB 8
#define PAIRS_PER_BLOCK (GROUPS_PER_BLOCK * PB)     // 128
#define CHUNKS_PER_BUCKET (CAP_B / PAIRS_PER_BLOCK) // 64

__global__ __launch_bounds__(THREADS, 3)
void pmf_sorted_kernel(const float* __restrict__ user_emb,
                       const float* __restrict__ item_emb,
                       float*       __restrict__ out)
{
    const int bucket = blockIdx.x / CHUNKS_PER_BUCKET;   // bucket-major order
    const int chunk  = blockIdx.x % CHUNKS_PER_BUCKET;
    const int count  = __ldg(&g_cnt[bucket]);
    const int cbase  = chunk * PAIRS_PER_BLOCK;
    if (cbase >= count) return;                          // over-provisioned chunk

    const int group = threadIdx.x >> 4;
    const int lane  = threadIdx.x & 15;
    const long long slab = (long long)bucket * CAP_B;
    const int base = cbase + group;

    // Phase 1: load packed records (independent).
    unsigned long long rec[PB];
    #pragma unroll
    for (int k = 0; k < PB; k++) {
        int j = base + k * GROUPS_PER_BLOCK;
        int q = (j < count) ? j : cbase;      // clamp inside valid region
        rec[k] = __ldg(&g_pairs[slab + q]);
    }

    // Phase 2: all row loads, independent, front-batched (16 LDG.128/thread).
    float4 u[PB], v[PB];
    #pragma unroll
    for (int k = 0; k < PB; k++) {
        int uid = (int)(rec[k] & ((1u << UID_BITS) - 1));
        int iid = (int)((rec[k] >> UID_BITS) & ((1u << IID_BITS) - 1));
        u[k] = __ldg(reinterpret_cast<const float4*>(
                   user_emb + (long long)uid * HIDDEN) + lane);
        v[k] = __ldg(reinterpret_cast<const float4*>(
                   item_emb + (long long)iid * HIDDEN) + lane);
    }

    // Phase 3: dot, 16-lane reduction, store to ORIGINAL index p.
    #pragma unroll
    for (int k = 0; k < PB; k++) {
        float acc = u[k].x * v[k].x + u[k].y * v[k].y
                  + u[k].z * v[k].z + u[k].w * v[k].w;
        acc += __shfl_xor_sync(0xFFFFFFFFu, acc, 8);
        acc += __shfl_xor_sync(0xFFFFFFFFu, acc, 4);
        acc += __shfl_xor_sync(0xFFFFFFFFu, acc, 2);
        acc += __shfl_xor_sync(0xFFFFFFFFu, acc, 1);
        int j = base + k * GROUPS_PER_BLOCK;
        if (lane == 0 && j < count) {
            int p = (int)(rec[k] >> (UID_BITS + IID_BITS));
            out[p] = fmaxf(acc, 0.0f);
        }
    }
}

// ---------------- fallback: direct (R4) ----------------
__global__ __launch_bounds__(THREADS, 3)
void pmf_direct_kernel(const float* __restrict__ user_emb,
                       const float* __restrict__ item_emb,
                       const int*   __restrict__ user_ids,
                       const int*   __restrict__ item_ids,
                       float*       __restrict__ out,
                       int num_pairs)
{
    const int group = threadIdx.x >> 4;
    const int lane  = threadIdx.x & 15;
    const int base  = blockIdx.x * PAIRS_PER_BLOCK + group;

    int uid[PB], iid[PB];
    #pragma unroll
    for (int k = 0; k < PB; k++) {
        int p = base + k * GROUPS_PER_BLOCK;
        int q = (p < num_pairs) ? p : 0;
        uid[k] = __ldg(&user_ids[q]);
        iid[k] = __ldg(&item_ids[q]);
    }
    float4 u[PB], v[PB];
    #pragma unroll
    for (int k = 0; k < PB; k++) {
        u[k] = __ldg(reinterpret_cast<const float4*>(
                   user_emb + (long long)uid[k] * HIDDEN) + lane);
        v[k] = __ldg(reinterpret_cast<const float4*>(
                   item_emb + (long long)iid[k] * HIDDEN) + lane);
    }
    #pragma unroll
    for (int k = 0; k < PB; k++) {
        float acc = u[k].x * v[k].x + u[k].y * v[k].y
                  + u[k].z * v[k].z + u[k].w * v[k].w;
        acc += __shfl_xor_sync(0xFFFFFFFFu, acc, 8);
        acc += __shfl_xor_sync(0xFFFFFFFFu, acc, 4);
        acc += __shfl_xor_sync(0xFFFFFFFFu, acc, 2);
        acc += __shfl_xor_sync(0xFFFFFFFFu, acc, 1);
        int p = base + k * GROUPS_PER_BLOCK;
        if (lane == 0 && p < num_pairs)
            out[p] = fmaxf(acc, 0.0f);
    }
}

extern "C" void kernel_launch(void* const* d_in, const int* in_sizes, int n_in,
                              void* d_out, int out_size)
{
    const float* user_emb = (const float*)d_in[0];
    const float* item_emb = (const float*)d_in[1];
    const int*   user_ids = (const int*)d_in[2];
    const int*   item_ids = (const int*)d_in[3];
    float*       out      = (float*)d_out;

    int num_pairs = in_sizes[2];
    long long num_users = in_sizes[0] / HIDDEN;
    long long num_items = in_sizes[1] / HIDDEN;

    // per-bucket capacity check: with 1M uniform users, mean 4090/bucket.
    // Require enough headroom that CAP_B overflow is impossible in the worst
    // plausible skew for this dataset shape; otherwise use direct kernel.
    bool can_bucket = (num_users <= (1LL << UID_BITS))
                   && (num_items <= (1LL << IID_BITS))
                   && (num_pairs <  (1  << 21))
                   && ((num_users >> BSHIFT) < BUCKETS)
                   && (num_pairs / (int)((num_users >> BSHIFT) + 1) * 3 / 2 < CAP_B);

    if (!can_bucket) {
        int blocks = (num_pairs + PAIRS_PER_BLOCK - 1) / PAIRS_PER_BLOCK;
        pmf_direct_kernel<<<blocks, THREADS>>>(
            user_emb, item_emb, user_ids, item_ids, out, num_pairs);
        return;
    }

    int sc_blocks = (num_pairs + SC_TILE - 1) / SC_TILE;

    zero_kernel<<<2, 256>>>();
    scatter_kernel<<<sc_blocks, SC_THREADS>>>(user_ids, item_ids, num_pairs);
    pmf_sorted_kernel<<<BUCKETS * CHUNKS_PER_BUCKET, THREADS>>>(
        user_emb, item_emb, out);
}

// round 8
// speedup vs baseline: 4.1226x; 4.1226x over previous
#include <cuda_runtime.h>
#include <cuda_bf16.h>

// PMF: out[p] = relu(dot(user_emb[user_ids[p]], item_emb[item_ids[p]])), D=64 fp32.
//
// R7b: same as R7 (compile fix: unsigned int instead of uint32_t).
// Direct kernel, no reordering. Stage gathered row chunks in SHARED via
// cp.async (LDGSTS.128) so in-flight bytes live in smem instead of the
// register file (R4's regs=76/occ=32% cap).
//   - 16 lanes per pair, one 16B chunk per lane per row (2 coalesced 128B
//     lines per 256B row).
//   - PB=4 pairs per group; each thread issues 8 cp.async.cg 16B copies,
//     commit, wait_group 0, then reads back ONLY ITS OWN 16B chunks
//     (no __syncthreads), dot + 16-lane shfl reduce, store.
//   - 32KB smem/CTA, ~40 regs -> ~6 CTAs/SM resident vs 3 for R4.

#define HIDDEN 64
#define THREADS 256
#define GROUPS_PER_BLOCK (THREADS / 16)            // 16
#define PB 4                                        // pairs per group
#define PAIRS_PER_BLOCK (GROUPS_PER_BLOCK * PB)     // 64

__device__ __forceinline__ void cp_async16(unsigned int smem_addr, const void* gptr) {
    asm volatile("cp.async.cg.shared.global [%0], [%1], 16;\n"
                 :: "r"(smem_addr), "l"(gptr));
}

__global__ __launch_bounds__(THREADS)
void pmf_kernel(const float* __restrict__ user_emb,
                const float* __restrict__ item_emb,
                const int*   __restrict__ user_ids,
                const int*   __restrict__ item_ids,
                float*       __restrict__ out,
                int num_pairs)
{
    // stage[uv][k][tid] : 2 * PB * 256 * 16B = 32KB
    __shared__ float4 stage[2][PB][THREADS];

    const int tid   = threadIdx.x;
    const int group = tid >> 4;            // 0..15
    const int lane  = tid & 15;            // 0..15
    const int base  = blockIdx.x * PAIRS_PER_BLOCK + group;

    // Phase 1: id loads (independent, front-batched).
    int uid[PB], iid[PB];
    #pragma unroll
    for (int k = 0; k < PB; k++) {
        int p = base + k * GROUPS_PER_BLOCK;
        int q = (p < num_pairs) ? p : 0;
        uid[k] = __ldg(&user_ids[q]);
        iid[k] = __ldg(&item_ids[q]);
    }

    // Phase 2: async-copy all row chunks to smem (8 LDGSTS.128 per thread,
    // fire-and-forget: no register pressure from in-flight data).
    unsigned int su = (unsigned int)__cvta_generic_to_shared(&stage[0][0][tid]);
    unsigned int sv = (unsigned int)__cvta_generic_to_shared(&stage[1][0][tid]);
    #pragma unroll
    for (int k = 0; k < PB; k++) {
        const float4* urow = reinterpret_cast<const float4*>(
            user_emb + (long long)uid[k] * HIDDEN) + lane;
        const float4* irow = reinterpret_cast<const float4*>(
            item_emb + (long long)iid[k] * HIDDEN) + lane;
        cp_async16(su + k * (THREADS * 16), urow);
        cp_async16(sv + k * (THREADS * 16), irow);
    }
    asm volatile("cp.async.commit_group;\n" ::: "memory");
    asm volatile("cp.async.wait_group 0;\n" ::: "memory");

    // Phase 3: each thread reads back its own chunks, dot, 16-lane reduce.
    #pragma unroll
    for (int k = 0; k < PB; k++) {
        float4 u = stage[0][k][tid];
        float4 v = stage[1][k][tid];
        float acc = u.x * v.x + u.y * v.y + u.z * v.z + u.w * v.w;
        acc += __shfl_xor_sync(0xFFFFFFFFu, acc, 8);
        acc += __shfl_xor_sync(0xFFFFFFFFu, acc, 4);
        acc += __shfl_xor_sync(0xFFFFFFFFu, acc, 2);
        acc += __shfl_xor_sync(0xFFFFFFFFu, acc, 1);
        int p = base + k * GROUPS_PER_BLOCK;
        if (lane == 0 && p < num_pairs)
            out[p] = fmaxf(acc, 0.0f);
    }
}

extern "C" void kernel_launch(void* const* d_in, const int* in_sizes, int n_in,
                              void* d_out, int out_size)
{
    const float* user_emb = (const float*)d_in[0];
    const float* item_emb = (const float*)d_in[1];
    const int*   user_ids = (const int*)d_in[2];
    const int*   item_ids = (const int*)d_in[3];
    float*       out      = (float*)d_out;

    int num_pairs = in_sizes[2];
    int blocks = (num_pairs + PAIRS_PER_BLOCK - 1) / PAIRS_PER_BLOCK;

    pmf_kernel<<<blocks, THREADS>>>(user_emb, item_emb, user_ids, item_ids,
                                    out, num_pairs);
}